// round 9
// baseline (speedup 1.0000x reference)
#include <cuda_runtime.h>
#include <cuda_bf16.h>
#include <cstdint>

// Problem constants
#define TT 512
#define BB 64
#define II 1024
#define HH 1024
#define GM (TT*BB)
#define GK II
#define GN HH

// Recurrent kernel config
#define NBLK 128
#define JPB  8
#define RTHREADS 256
#define RCHUNK 128
#define NCH (HH / RCHUNK)       // 8
#define CHUNK_U32 (BB * RCHUNK) // 8192 u32 = 32KB per chunk

// Scratch
__device__ float    g_gates[(size_t)3 * TT * BB * HH];
__device__ float    g_h  [(size_t)BB * HH];        // fp32 h (elementwise use)
__device__ uint32_t g_htf [(size_t)BB * HH];       // tf32 h, chunked+swizzled
__device__ uint32_t g_hrtf[(size_t)BB * HH];       // tf32 h*r, chunked+swizzled
// Per-chunk ready counters (monotonic, reset by host memset each launch).
// [0..NCH): h chunks; [NCH..2*NCH): h*r chunks. Padded 32 u32 = 128B apart.
__device__ unsigned g_rdy[2 * NCH * 32];
#define RDY_H(c)  ((c) * 32)
#define RDY_HR(c) ((NCH + (c)) * 32)

// tf32-chunked layout: addr(b,j) = (j>>7)*8192 + b*128 + ((j&127) ^ ((b&7)<<2))

__device__ __forceinline__ float sigmoidf_(float x) {
    return 1.0f / (1.0f + __expf(-x));
}

__device__ __forceinline__ uint32_t f2tf32(float x) {
    uint32_t r;
    asm("cvt.rna.tf32.f32 %0, %1;" : "=r"(r) : "f"(x));
    return r;
}

__device__ __forceinline__ void mma_tf32(float acc[4],
                                         uint32_t a0, uint32_t a1, uint32_t a2, uint32_t a3,
                                         uint32_t b0, uint32_t b1) {
    asm volatile(
        "mma.sync.aligned.m16n8k8.row.col.f32.tf32.tf32.f32 "
        "{%0,%1,%2,%3}, {%4,%5,%6,%7}, {%8,%9}, {%0,%1,%2,%3};"
        : "+f"(acc[0]), "+f"(acc[1]), "+f"(acc[2]), "+f"(acc[3])
        : "r"(a0), "r"(a1), "r"(a2), "r"(a3), "r"(b0), "r"(b1));
}

__device__ __forceinline__ void mbarInit(uint32_t mbar) {
    asm volatile("mbarrier.init.shared::cta.b64 [%0], 1;" :: "r"(mbar) : "memory");
}

__device__ __forceinline__ void bulkStage(uint32_t dst, const uint32_t* __restrict__ gsrc,
                                          uint32_t mbar) {
    asm volatile("mbarrier.arrive.expect_tx.shared::cta.b64 _, [%0], %1;"
                 :: "r"(mbar), "r"(32768u) : "memory");
    asm volatile("cp.async.bulk.shared::cta.global.mbarrier::complete_tx::bytes "
                 "[%0], [%1], %2, [%3];"
                 :: "r"(dst), "l"(gsrc), "r"(32768u), "r"(mbar) : "memory");
}

__device__ __forceinline__ void mbarWait(uint32_t mbar, uint32_t parity) {
    uint32_t done;
    do {
        asm volatile(
            "{\n\t.reg .pred p;\n\t"
            "mbarrier.try_wait.parity.acquire.cta.shared::cta.b64 p, [%1], %2;\n\t"
            "selp.b32 %0, 1, 0, p;\n\t}"
            : "=r"(done) : "r"(mbar), "r"(parity) : "memory");
    } while (!done);
}

// Spin until counter >= target (acquire).
__device__ __forceinline__ void spinGE(const unsigned* ctr, unsigned target) {
    volatile const unsigned* v = ctr;
    while (*v < target) { }
    __threadfence();
}

// ---------------------------------------------------------------------------
// TF32 input projection GEMM (unchanged, ~2ms)
// ---------------------------------------------------------------------------
#define BKT 32
#define SASTRIDE 136

__global__ __launch_bounds__(256) void mma_gate(
    const float* __restrict__ A,
    const float* __restrict__ W0, const float* __restrict__ W1, const float* __restrict__ W2,
    const float* __restrict__ b0, const float* __restrict__ b1, const float* __restrict__ b2)
{
    __shared__ uint32_t As[BKT * SASTRIDE];
    __shared__ uint32_t Ws[BKT * SASTRIDE];

    const int gate = blockIdx.z;
    const float* W    = (gate == 0) ? W0 : (gate == 1) ? W1 : W2;
    const float* bias = (gate == 0) ? b0 : (gate == 1) ? b1 : b2;
    float* C = g_gates + (size_t)gate * GM * GN;

    const int m0 = blockIdx.y * 128;
    const int n0 = blockIdx.x * 128;
    const int tid  = threadIdx.x;
    const int wid  = tid >> 5;
    const int lane = tid & 31;
    const int g  = lane >> 2;
    const int t4 = lane & 3;

    const int wm = (wid & 1) * 64;
    const int wn = (wid >> 1) * 32;

    float acc[4][4][4];
    #pragma unroll
    for (int mi = 0; mi < 4; ++mi)
        #pragma unroll
        for (int ni = 0; ni < 4; ++ni)
            #pragma unroll
            for (int r = 0; r < 4; ++r) acc[mi][ni][r] = 0.0f;

    for (int kt = 0; kt < GK; kt += BKT) {
        #pragma unroll
        for (int i = 0; i < 4; ++i) {
            int idx = tid + i * 256;
            int row = idx >> 3;
            int kc4 = (idx & 7) * 4;
            float4 a = *(const float4*)&A[(size_t)(m0 + row) * GK + kt + kc4];
            As[(kc4 + 0) * SASTRIDE + row] = f2tf32(a.x);
            As[(kc4 + 1) * SASTRIDE + row] = f2tf32(a.y);
            As[(kc4 + 2) * SASTRIDE + row] = f2tf32(a.z);
            As[(kc4 + 3) * SASTRIDE + row] = f2tf32(a.w);
            float4 w = *(const float4*)&W[(size_t)(n0 + row) * GK + kt + kc4];
            Ws[(kc4 + 0) * SASTRIDE + row] = f2tf32(w.x);
            Ws[(kc4 + 1) * SASTRIDE + row] = f2tf32(w.y);
            Ws[(kc4 + 2) * SASTRIDE + row] = f2tf32(w.z);
            Ws[(kc4 + 3) * SASTRIDE + row] = f2tf32(w.w);
        }
        __syncthreads();

        #pragma unroll
        for (int ks = 0; ks < BKT; ks += 8) {
            uint32_t af[4][4];
            #pragma unroll
            for (int mi = 0; mi < 4; ++mi) {
                int m = wm + mi * 16 + g;
                af[mi][0] = As[(ks + t4    ) * SASTRIDE + m    ];
                af[mi][1] = As[(ks + t4    ) * SASTRIDE + m + 8];
                af[mi][2] = As[(ks + t4 + 4) * SASTRIDE + m    ];
                af[mi][3] = As[(ks + t4 + 4) * SASTRIDE + m + 8];
            }
            uint32_t bf[4][2];
            #pragma unroll
            for (int ni = 0; ni < 4; ++ni) {
                int n = wn + ni * 8 + g;
                bf[ni][0] = Ws[(ks + t4    ) * SASTRIDE + n];
                bf[ni][1] = Ws[(ks + t4 + 4) * SASTRIDE + n];
            }
            #pragma unroll
            for (int mi = 0; mi < 4; ++mi)
                #pragma unroll
                for (int ni = 0; ni < 4; ++ni)
                    mma_tf32(acc[mi][ni], af[mi][0], af[mi][1], af[mi][2], af[mi][3],
                             bf[ni][0], bf[ni][1]);
        }
        __syncthreads();
    }

    #pragma unroll
    for (int mi = 0; mi < 4; ++mi) {
        int mrow = m0 + wm + mi * 16 + g;
        #pragma unroll
        for (int ni = 0; ni < 4; ++ni) {
            int col = n0 + wn + ni * 8 + 2 * t4;
            float bx = bias[col], by = bias[col + 1];
            float2 o0 = make_float2(acc[mi][ni][0] + bx, acc[mi][ni][1] + by);
            float2 o1 = make_float2(acc[mi][ni][2] + bx, acc[mi][ni][3] + by);
            *(float2*)&C[(size_t)mrow * GN + col] = o0;
            *(float2*)&C[(size_t)(mrow + 8) * GN + col] = o1;
        }
    }
}

// ---------------------------------------------------------------------------
// R9 recurrent kernel: R8 bulk-staged tf32 pipeline, but NO grid barriers —
// per-chunk monotonic ready counters gate each bulk copy instead.
// ---------------------------------------------------------------------------
#define OFF_WF   0
#define SZ_WF    (3 * 128 * 32 * 8)                 // 98304
#define OFF_SB0  (OFF_WF + SZ_WF)                   // 32KB buffer 0
#define OFF_SB1  (OFF_SB0 + 32768)
#define OFF_MBAR (OFF_SB1 + 32768)                  // 2 mbarriers (16 B)
#define OFF_SZ   (OFF_MBAR + 16)
#define SZ_SZ    (BB * JPB * 4)
#define OFF_SHO  (OFF_SZ + SZ_SZ)
#define OFF_SRED (OFF_SHO + SZ_SZ)
#define SZ_SRED  (4 * 32 * 4 * 4)
#define RSMEM_BYTES (OFF_SRED + SZ_SRED)            // ~170KB

__global__ __launch_bounds__(RTHREADS, 1) void gru_recurrent(
    const float* __restrict__ state,
    const float* __restrict__ w_hr,
    const float* __restrict__ w_hz,
    const float* __restrict__ w_hh,
    float* __restrict__ out,
    int out_size)
{
    extern __shared__ char smem[];
    uint2*    uWf  = (uint2*)(smem + OFF_WF);
    uint32_t* sHg[2];
    sHg[0] = (uint32_t*)(smem + OFF_SB0);
    sHg[1] = (uint32_t*)(smem + OFF_SB1);
    float*    sZ    = (float*)(smem + OFF_SZ);
    float*    sHold = (float*)(smem + OFF_SHO);
    float*    sRed  = (float*)(smem + OFF_SRED);

    uint32_t sBuf[2], mb[2];
    sBuf[0] = (uint32_t)__cvta_generic_to_shared(sHg[0]);
    sBuf[1] = (uint32_t)__cvta_generic_to_shared(sHg[1]);
    mb[0] = (uint32_t)__cvta_generic_to_shared(smem + OFF_MBAR);
    mb[1] = mb[0] + 8;

    const int j0  = blockIdx.x * JPB;
    const int myChunk = blockIdx.x >> 4;   // chunk this CTA's columns live in
    const int tid = threadIdx.x;
    const int wid = tid >> 5;
    const int lane = tid & 31;
    const int g  = lane >> 2;
    const int t4 = lane & 3;
    const int gx = g << 2;           // XOR swizzle key

    if (tid == 0) { mbarInit(mb[0]); mbarInit(mb[1]); }

    // ---- weights -> tf32 B-fragment order (once) ----
    {
        const float* Ws3[3] = {w_hr, w_hz, w_hh};
        for (int g3 = 0; g3 < 3; ++g3) {
            const float* W = Ws3[g3];
            for (int idx = tid; idx < 128 * 32; idx += RTHREADS) {
                int kk8 = idx >> 5;
                int ln  = idx & 31;
                int jj  = ln >> 2;
                int kk  = (kk8 << 3) + (ln & 3);
                uint2 v;
                v.x = f2tf32(W[(size_t)(j0 + jj) * HH + kk]);
                v.y = f2tf32(W[(size_t)(j0 + jj) * HH + kk + 4]);
                uWf[(g3 * 128 + kk8) * 32 + ln] = v;
            }
        }
    }

    // ---- init h (fp32 + tf32 swizzled) for my columns, then signal ----
    for (int p = tid; p < BB * JPB; p += RTHREADS) {
        int b = p >> 3, jj = p & 7;
        int j = j0 + jj;
        float v = state[(size_t)b * HH + j];
        g_h[(size_t)b * HH + j] = v;
        g_htf[(size_t)(j >> 7) * CHUNK_U32 + b * 128 + ((j & 127) ^ ((b & 7) << 2))] = f2tf32(v);
    }
    __syncthreads();
    if (tid == 0) {
        __threadfence();
        atomicAdd(&g_rdy[RDY_H(myChunk)], 1u);
    }

    const float* gatesR = g_gates;
    const float* gatesZ = g_gates + (size_t)1 * TT * BB * HH;
    const float* gatesH = g_gates + (size_t)2 * TT * BB * HH;
    const bool hasFinal = (out_size >= (int)((size_t)TT * BB * HH + BB * HH));
    float* finalOut = out + (size_t)TT * BB * HH;

    const int miA = wid & 3;
    const int niA = wid >> 2;        // 0 = r gate, 1 = z gate
    const int m0A = miA * 16;
    const int miB = wid & 3;
    const int khB = wid >> 2;        // chunks 0-3 vs 4-7

    const int jA2 = 2 * t4;
    const int bA0 = m0A + g, bA1 = bA0 + 8;
    const int jc  = j0 + jA2;
    const int tfW0 = (jc >> 7) * CHUNK_U32 + bA0 * 128 + ((jc & 127) ^ gx);
    const int tfW1 = (jc >> 7) * CHUNK_U32 + bA1 * 128 + ((jc & 127) ^ gx);

    unsigned par0 = 0, par1 = 0;

    for (int t = 0; t < TT; ++t) {
        const size_t baseT = (size_t)t * BB * HH;
        const unsigned tgt = 16u * (unsigned)(t + 1);

        // Prefetch epilogue-A operands (own columns; written by own CTA)
        const float* gAB = (niA == 0) ? gatesR : gatesZ;
        float2 pg0 = *(const float2*)&gAB[baseT + (size_t)bA0 * HH + jc];
        float2 pg1 = *(const float2*)&gAB[baseT + (size_t)bA1 * HH + jc];
        float2 ho0 = *(const float2*)&g_h[(size_t)bA0 * HH + jc];
        float2 ho1 = *(const float2*)&g_h[(size_t)bA1 * HH + jc];

        // ================= Phase A: r and z =================
        float acc[4] = {0.f, 0.f, 0.f, 0.f};
        if (tid == 0) {
            spinGE(&g_rdy[RDY_H(0)], tgt);
            bulkStage(sBuf[0], g_htf, mb[0]);
            spinGE(&g_rdy[RDY_H(1)], tgt);
            bulkStage(sBuf[1], g_htf + CHUNK_U32, mb[1]);
        }
        #pragma unroll 1
        for (int c = 0; c < NCH; ++c) {
            unsigned& par = (c & 1) ? par1 : par0;
            mbarWait(mb[c & 1], par & 1u);
            par++;
            const uint32_t* buf = sHg[c & 1];
            const uint2* wf = &uWf[(niA * 128 + c * 16) * 32 + lane];
            #pragma unroll
            for (int kk = 0; kk < RCHUNK / 8; ++kk) {
                int k0 = (kk * 8 + t4) ^ gx;
                int k1 = (kk * 8 + t4 + 4) ^ gx;
                uint32_t a0 = buf[bA0 * 128 + k0];
                uint32_t a1 = buf[bA1 * 128 + k0];
                uint32_t a2 = buf[bA0 * 128 + k1];
                uint32_t a3 = buf[bA1 * 128 + k1];
                uint2 b2 = wf[kk * 32];
                mma_tf32(acc, a0, a1, a2, a3, b2.x, b2.y);
            }
            __syncthreads();     // all warps done with buf -> safe to re-stage
            if (c + 2 < NCH && tid == 0) {
                spinGE(&g_rdy[RDY_H(c + 2)], tgt);
                bulkStage(sBuf[c & 1], g_htf + (size_t)(c + 2) * CHUNK_U32, mb[c & 1]);
            }
        }

        // Epilogue A
        if (niA == 0) {
            float r00 = sigmoidf_(pg0.x + acc[0]);
            float r01 = sigmoidf_(pg0.y + acc[1]);
            float r10 = sigmoidf_(pg1.x + acc[2]);
            float r11 = sigmoidf_(pg1.y + acc[3]);
            uint2 w0, w1;
            w0.x = f2tf32(ho0.x * r00); w0.y = f2tf32(ho0.y * r01);
            w1.x = f2tf32(ho1.x * r10); w1.y = f2tf32(ho1.y * r11);
            *(uint2*)&g_hrtf[tfW0] = w0;
            *(uint2*)&g_hrtf[tfW1] = w1;
            *(float2*)&sHold[bA0 * JPB + jA2] = ho0;
            *(float2*)&sHold[bA1 * JPB + jA2] = ho1;
        } else {
            *(float2*)&sZ[bA0 * JPB + jA2] =
                make_float2(sigmoidf_(pg0.x + acc[0]), sigmoidf_(pg0.y + acc[1]));
            *(float2*)&sZ[bA1 * JPB + jA2] =
                make_float2(sigmoidf_(pg1.x + acc[2]), sigmoidf_(pg1.y + acc[3]));
        }
        __syncthreads();
        if (tid == 0) {
            __threadfence();
            atomicAdd(&g_rdy[RDY_HR(myChunk)], 1u);   // my h*r chunk contribution
        }

        // Prefetch candidate gates
        float2 pgh0 = *(const float2*)&gatesH[baseT + (size_t)bA0 * HH + jc];
        float2 pgh1 = *(const float2*)&gatesH[baseT + (size_t)bA1 * HH + jc];

        // ================= Phase B: candidate =================
        float accB[4] = {0.f, 0.f, 0.f, 0.f};
        if (tid == 0) {
            spinGE(&g_rdy[RDY_HR(0)], tgt);
            bulkStage(sBuf[0], g_hrtf, mb[0]);
            spinGE(&g_rdy[RDY_HR(1)], tgt);
            bulkStage(sBuf[1], g_hrtf + CHUNK_U32, mb[1]);
        }
        #pragma unroll 1
        for (int c = 0; c < NCH; ++c) {
            unsigned& par = (c & 1) ? par1 : par0;
            mbarWait(mb[c & 1], par & 1u);
            par++;
            if ((c >> 2) == khB) {
                const uint32_t* buf = sHg[c & 1];
                const uint2* wf = &uWf[(2 * 128 + c * 16) * 32 + lane];
                const int bB0 = miB * 16 + g, bB1 = bB0 + 8;
                #pragma unroll
                for (int kk = 0; kk < RCHUNK / 8; ++kk) {
                    int k0 = (kk * 8 + t4) ^ gx;
                    int k1 = (kk * 8 + t4 + 4) ^ gx;
                    uint32_t a0 = buf[bB0 * 128 + k0];
                    uint32_t a1 = buf[bB1 * 128 + k0];
                    uint32_t a2 = buf[bB0 * 128 + k1];
                    uint32_t a3 = buf[bB1 * 128 + k1];
                    uint2 b2 = wf[kk * 32];
                    mma_tf32(accB, a0, a1, a2, a3, b2.x, b2.y);
                }
            }
            __syncthreads();
            if (c + 2 < NCH && tid == 0) {
                spinGE(&g_rdy[RDY_HR(c + 2)], tgt);
                bulkStage(sBuf[c & 1], g_hrtf + (size_t)(c + 2) * CHUNK_U32, mb[c & 1]);
            }
        }

        if (khB == 1) {
            *(float4*)&sRed[(miB * 32 + lane) * 4] =
                make_float4(accB[0], accB[1], accB[2], accB[3]);
        }
        __syncthreads();
        if (khB == 0) {
            float4 p = *(const float4*)&sRed[(miB * 32 + lane) * 4];
            accB[0] += p.x; accB[1] += p.y; accB[2] += p.z; accB[3] += p.w;

            int b0 = miB * 16 + g, b1 = b0 + 8;
            float c00 = tanhf(pgh0.x + accB[0]);
            float c01 = tanhf(pgh0.y + accB[1]);
            float c10 = tanhf(pgh1.x + accB[2]);
            float c11 = tanhf(pgh1.y + accB[3]);
            float2 z0 = *(const float2*)&sZ[b0 * JPB + jA2];
            float2 z1 = *(const float2*)&sZ[b1 * JPB + jA2];
            float2 h0 = *(const float2*)&sHold[b0 * JPB + jA2];
            float2 h1 = *(const float2*)&sHold[b1 * JPB + jA2];
            float2 hn0 = make_float2(z0.x * h0.x + (1.f - z0.x) * c00,
                                     z0.y * h0.y + (1.f - z0.y) * c01);
            float2 hn1 = make_float2(z1.x * h1.x + (1.f - z1.x) * c10,
                                     z1.y * h1.y + (1.f - z1.y) * c11);
            *(float2*)&g_h[(size_t)b0 * HH + jc] = hn0;
            *(float2*)&g_h[(size_t)b1 * HH + jc] = hn1;
            uint2 w0, w1;
            w0.x = f2tf32(hn0.x); w0.y = f2tf32(hn0.y);
            w1.x = f2tf32(hn1.x); w1.y = f2tf32(hn1.y);
            *(uint2*)&g_htf[tfW0] = w0;
            *(uint2*)&g_htf[tfW1] = w1;
            *(float2*)&out[baseT + (size_t)b0 * HH + jc] = hn0;
            *(float2*)&out[baseT + (size_t)b1 * HH + jc] = hn1;
            if (hasFinal && t == TT - 1) {
                *(float2*)&finalOut[(size_t)b0 * HH + jc] = hn0;
                *(float2*)&finalOut[(size_t)b1 * HH + jc] = hn1;
            }
        }
        __syncthreads();
        if (tid == 0) {
            __threadfence();
            atomicAdd(&g_rdy[RDY_H(myChunk)], 1u);    // h(t+1) chunk contribution
        }
    }
}

// ---------------------------------------------------------------------------
extern "C" void kernel_launch(void* const* d_in, const int* in_sizes, int n_in,
                              void* d_out, int out_size)
{
    const float* x      = (const float*)d_in[0];
    const float* state  = (const float*)d_in[1];
    const float* w_xr_w = (const float*)d_in[2];
    const float* w_xr_b = (const float*)d_in[3];
    const float* w_hr_w = (const float*)d_in[4];
    const float* w_xz_w = (const float*)d_in[5];
    const float* w_xz_b = (const float*)d_in[6];
    const float* w_hz_w = (const float*)d_in[7];
    const float* w_xh_w = (const float*)d_in[8];
    const float* w_xh_b = (const float*)d_in[9];
    const float* w_hh_w = (const float*)d_in[10];

    cudaFuncSetAttribute(gru_recurrent,
                         cudaFuncAttributeMaxDynamicSharedMemorySize, RSMEM_BYTES);

    // Reset ready counters (graph-capturable async memset, no allocation).
    void* rdyPtr = nullptr;
    cudaGetSymbolAddress(&rdyPtr, g_rdy);
    cudaMemsetAsync(rdyPtr, 0, sizeof(unsigned) * 2 * NCH * 32);

    dim3 gg(GN / 128, GM / 128, 3);
    mma_gate<<<gg, 256>>>(x, w_xr_w, w_xz_w, w_xh_w, w_xr_b, w_xz_b, w_xh_b);

    gru_recurrent<<<NBLK, RTHREADS, RSMEM_BYTES>>>(
        state, w_hr_w, w_hz_w, w_hh_w, (float*)d_out, out_size);
}

// round 10
// speedup vs baseline: 1.7754x; 1.7754x over previous
#include <cuda_runtime.h>
#include <cuda_bf16.h>
#include <cstdint>

// Problem constants
#define TT 512
#define BB 64
#define II 1024
#define HH 1024
#define GM (TT*BB)
#define GK II
#define GN HH

// Recurrent kernel config (fp16 path)
#define NBLK 128
#define JPB  8
#define RTHREADS 256
#define RCHUNK 256               // k per chunk (fp16 -> 32KB buffer)
#define NCH (HH / RCHUNK)        // 4
#define CHUNK_U32 (BB * RCHUNK / 2)  // 8192 u32 words per chunk (fp16 pairs)

// Scratch
__device__ float    g_gates[(size_t)3 * TT * BB * HH];
__device__ float    g_h   [(size_t)BB * HH];       // fp32 h (elementwise use)
__device__ uint32_t g_hf16 [(size_t)BB * HH / 2];  // fp16-pair h, chunked+swizzled
__device__ uint32_t g_hrf16[(size_t)BB * HH / 2];  // fp16-pair h*r
__device__ unsigned g_bar_cnt;
__device__ unsigned g_bar_gen;

// fp16-pair layout: word(b,j) = (j>>8)*CHUNK_U32 + b*128 + (((j&255)>>1) ^ ((b&7)<<2))
// (j even; word holds {h[b][j], h[b][j+1]})

// ---------------------------------------------------------------------------
__device__ __forceinline__ void gridBarrier() {
    __syncthreads();
    if (threadIdx.x == 0) {
        __threadfence();
        volatile unsigned* vgen = &g_bar_gen;
        unsigned gen = *vgen;
        if (atomicAdd(&g_bar_cnt, 1u) == NBLK - 1u) {
            g_bar_cnt = 0u;
            __threadfence();
            *vgen = gen + 1u;
        } else {
            while (*vgen == gen) { }
        }
        __threadfence();
    }
    __syncthreads();
}

__device__ __forceinline__ float sigmoidf_(float x) {
    return 1.0f / (1.0f + __expf(-x));
}

__device__ __forceinline__ uint32_t f2tf32(float x) {
    uint32_t r;
    asm("cvt.rna.tf32.f32 %0, %1;" : "=r"(r) : "f"(x));
    return r;
}

// pack two floats into fp16x2: low half = lo, high half = hi
__device__ __forceinline__ uint32_t f2h2(float lo, float hi) {
    uint32_t r;
    asm("cvt.rn.f16x2.f32 %0, %1, %2;" : "=r"(r) : "f"(hi), "f"(lo));
    return r;
}

__device__ __forceinline__ void mma_tf32(float acc[4],
                                         uint32_t a0, uint32_t a1, uint32_t a2, uint32_t a3,
                                         uint32_t b0, uint32_t b1) {
    asm volatile(
        "mma.sync.aligned.m16n8k8.row.col.f32.tf32.tf32.f32 "
        "{%0,%1,%2,%3}, {%4,%5,%6,%7}, {%8,%9}, {%0,%1,%2,%3};"
        : "+f"(acc[0]), "+f"(acc[1]), "+f"(acc[2]), "+f"(acc[3])
        : "r"(a0), "r"(a1), "r"(a2), "r"(a3), "r"(b0), "r"(b1));
}

__device__ __forceinline__ void mma_f16(float acc[4],
                                        uint32_t a0, uint32_t a1, uint32_t a2, uint32_t a3,
                                        uint32_t b0, uint32_t b1) {
    asm volatile(
        "mma.sync.aligned.m16n8k16.row.col.f32.f16.f16.f32 "
        "{%0,%1,%2,%3}, {%4,%5,%6,%7}, {%8,%9}, {%0,%1,%2,%3};"
        : "+f"(acc[0]), "+f"(acc[1]), "+f"(acc[2]), "+f"(acc[3])
        : "r"(a0), "r"(a1), "r"(a2), "r"(a3), "r"(b0), "r"(b1));
}

__device__ __forceinline__ void mbarInit(uint32_t mbar) {
    asm volatile("mbarrier.init.shared::cta.b64 [%0], 1;" :: "r"(mbar) : "memory");
}

__device__ __forceinline__ void bulkStage(uint32_t dst, const uint32_t* __restrict__ gsrc,
                                          uint32_t mbar) {
    asm volatile("mbarrier.arrive.expect_tx.shared::cta.b64 _, [%0], %1;"
                 :: "r"(mbar), "r"(32768u) : "memory");
    asm volatile("cp.async.bulk.shared::cta.global.mbarrier::complete_tx::bytes "
                 "[%0], [%1], %2, [%3];"
                 :: "r"(dst), "l"(gsrc), "r"(32768u), "r"(mbar) : "memory");
}

__device__ __forceinline__ void mbarWait(uint32_t mbar, uint32_t parity) {
    uint32_t done;
    do {
        asm volatile(
            "{\n\t.reg .pred p;\n\t"
            "mbarrier.try_wait.parity.acquire.cta.shared::cta.b64 p, [%1], %2;\n\t"
            "selp.b32 %0, 1, 0, p;\n\t}"
            : "=r"(done) : "r"(mbar), "r"(parity) : "memory");
    } while (!done);
}

// ---------------------------------------------------------------------------
// TF32 input projection GEMM (unchanged, ~2ms)
// ---------------------------------------------------------------------------
#define BKT 32
#define SASTRIDE 136

__global__ __launch_bounds__(256) void mma_gate(
    const float* __restrict__ A,
    const float* __restrict__ W0, const float* __restrict__ W1, const float* __restrict__ W2,
    const float* __restrict__ b0, const float* __restrict__ b1, const float* __restrict__ b2)
{
    __shared__ uint32_t As[BKT * SASTRIDE];
    __shared__ uint32_t Ws[BKT * SASTRIDE];

    const int gate = blockIdx.z;
    const float* W    = (gate == 0) ? W0 : (gate == 1) ? W1 : W2;
    const float* bias = (gate == 0) ? b0 : (gate == 1) ? b1 : b2;
    float* C = g_gates + (size_t)gate * GM * GN;

    const int m0 = blockIdx.y * 128;
    const int n0 = blockIdx.x * 128;
    const int tid  = threadIdx.x;
    const int wid  = tid >> 5;
    const int lane = tid & 31;
    const int g  = lane >> 2;
    const int t4 = lane & 3;

    const int wm = (wid & 1) * 64;
    const int wn = (wid >> 1) * 32;

    float acc[4][4][4];
    #pragma unroll
    for (int mi = 0; mi < 4; ++mi)
        #pragma unroll
        for (int ni = 0; ni < 4; ++ni)
            #pragma unroll
            for (int r = 0; r < 4; ++r) acc[mi][ni][r] = 0.0f;

    for (int kt = 0; kt < GK; kt += BKT) {
        #pragma unroll
        for (int i = 0; i < 4; ++i) {
            int idx = tid + i * 256;
            int row = idx >> 3;
            int kc4 = (idx & 7) * 4;
            float4 a = *(const float4*)&A[(size_t)(m0 + row) * GK + kt + kc4];
            As[(kc4 + 0) * SASTRIDE + row] = f2tf32(a.x);
            As[(kc4 + 1) * SASTRIDE + row] = f2tf32(a.y);
            As[(kc4 + 2) * SASTRIDE + row] = f2tf32(a.z);
            As[(kc4 + 3) * SASTRIDE + row] = f2tf32(a.w);
            float4 w = *(const float4*)&W[(size_t)(n0 + row) * GK + kt + kc4];
            Ws[(kc4 + 0) * SASTRIDE + row] = f2tf32(w.x);
            Ws[(kc4 + 1) * SASTRIDE + row] = f2tf32(w.y);
            Ws[(kc4 + 2) * SASTRIDE + row] = f2tf32(w.z);
            Ws[(kc4 + 3) * SASTRIDE + row] = f2tf32(w.w);
        }
        __syncthreads();

        #pragma unroll
        for (int ks = 0; ks < BKT; ks += 8) {
            uint32_t af[4][4];
            #pragma unroll
            for (int mi = 0; mi < 4; ++mi) {
                int m = wm + mi * 16 + g;
                af[mi][0] = As[(ks + t4    ) * SASTRIDE + m    ];
                af[mi][1] = As[(ks + t4    ) * SASTRIDE + m + 8];
                af[mi][2] = As[(ks + t4 + 4) * SASTRIDE + m    ];
                af[mi][3] = As[(ks + t4 + 4) * SASTRIDE + m + 8];
            }
            uint32_t bf[4][2];
            #pragma unroll
            for (int ni = 0; ni < 4; ++ni) {
                int n = wn + ni * 8 + g;
                bf[ni][0] = Ws[(ks + t4    ) * SASTRIDE + n];
                bf[ni][1] = Ws[(ks + t4 + 4) * SASTRIDE + n];
            }
            #pragma unroll
            for (int mi = 0; mi < 4; ++mi)
                #pragma unroll
                for (int ni = 0; ni < 4; ++ni)
                    mma_tf32(acc[mi][ni], af[mi][0], af[mi][1], af[mi][2], af[mi][3],
                             bf[ni][0], bf[ni][1]);
        }
        __syncthreads();
    }

    #pragma unroll
    for (int mi = 0; mi < 4; ++mi) {
        int mrow = m0 + wm + mi * 16 + g;
        #pragma unroll
        for (int ni = 0; ni < 4; ++ni) {
            int col = n0 + wn + ni * 8 + 2 * t4;
            float bx = bias[col], by = bias[col + 1];
            float2 o0 = make_float2(acc[mi][ni][0] + bx, acc[mi][ni][1] + by);
            float2 o1 = make_float2(acc[mi][ni][2] + bx, acc[mi][ni][3] + by);
            *(float2*)&C[(size_t)mrow * GN + col] = o0;
            *(float2*)&C[(size_t)(mrow + 8) * GN + col] = o1;
        }
    }
}

// ---------------------------------------------------------------------------
// R10 recurrent kernel: fp16 m16n8k16 MMA, fp16-pair h staging (half the
// crossbar bytes of R8), 256-k chunks (half the syncs), R8 gridBarrier.
// ---------------------------------------------------------------------------
#define OFF_WF   0
#define SZ_WF    (3 * 64 * 32 * 8)                  // 49152 (fp16 weight frags)
#define OFF_SB0  (OFF_WF + SZ_WF)                   // 32KB buffer 0
#define OFF_SB1  (OFF_SB0 + 32768)
#define OFF_MBAR (OFF_SB1 + 32768)                  // 2 mbarriers
#define OFF_SZ   (OFF_MBAR + 16)
#define SZ_SZ    (BB * JPB * 4)
#define OFF_SHO  (OFF_SZ + SZ_SZ)
#define OFF_SRED (OFF_SHO + SZ_SZ)
#define SZ_SRED  (4 * 32 * 4 * 4)
#define RSMEM_BYTES (OFF_SRED + SZ_SRED)            // ~121KB

__global__ __launch_bounds__(RTHREADS, 1) void gru_recurrent(
    const float* __restrict__ state,
    const float* __restrict__ w_hr,
    const float* __restrict__ w_hz,
    const float* __restrict__ w_hh,
    float* __restrict__ out,
    int out_size)
{
    extern __shared__ char smem[];
    uint2*    uWf  = (uint2*)(smem + OFF_WF);       // [g3][kk16][lane] fp16 B-frags
    uint32_t* sHg[2];
    sHg[0] = (uint32_t*)(smem + OFF_SB0);
    sHg[1] = (uint32_t*)(smem + OFF_SB1);
    float*    sZ    = (float*)(smem + OFF_SZ);
    float*    sHold = (float*)(smem + OFF_SHO);
    float*    sRed  = (float*)(smem + OFF_SRED);

    uint32_t sBuf[2], mb[2];
    sBuf[0] = (uint32_t)__cvta_generic_to_shared(sHg[0]);
    sBuf[1] = (uint32_t)__cvta_generic_to_shared(sHg[1]);
    mb[0] = (uint32_t)__cvta_generic_to_shared(smem + OFF_MBAR);
    mb[1] = mb[0] + 8;

    const int j0  = blockIdx.x * JPB;
    const int tid = threadIdx.x;
    const int wid = tid >> 5;
    const int lane = tid & 31;
    const int g  = lane >> 2;
    const int t4 = lane & 3;
    const int gx = g << 2;           // XOR swizzle key (= (b&7)<<2 for rows g, g+8)

    if (tid == 0) { mbarInit(mb[0]); mbarInit(mb[1]); }

    // ---- weights -> fp16 B-fragment order (once) ----
    // For gate g3, k16-step kk (0..63), lane ln: col jj=ln>>2, t4w=ln&3:
    //   v.x = {W[j][kk*16+2t4w], W[j][kk*16+2t4w+1]}
    //   v.y = {W[j][kk*16+2t4w+8], W[j][kk*16+2t4w+9]}
    {
        const float* Ws3[3] = {w_hr, w_hz, w_hh};
        for (int g3 = 0; g3 < 3; ++g3) {
            const float* W = Ws3[g3];
            for (int idx = tid; idx < 64 * 32; idx += RTHREADS) {
                int kk  = idx >> 5;
                int ln  = idx & 31;
                int jj  = ln >> 2;
                int k0  = (kk << 4) + ((ln & 3) << 1);
                const float* Wr = &W[(size_t)(j0 + jj) * HH];
                uint2 v;
                v.x = f2h2(Wr[k0],     Wr[k0 + 1]);
                v.y = f2h2(Wr[k0 + 8], Wr[k0 + 9]);
                uWf[(g3 * 64 + kk) * 32 + ln] = v;
            }
        }
    }

    // ---- init h (fp32 + fp16-pair swizzled) for my columns ----
    for (int p = tid; p < BB * JPB; p += RTHREADS) {
        int b = p >> 3, jj = p & 7;
        int j = j0 + jj;
        g_h[(size_t)b * HH + j] = state[(size_t)b * HH + j];
    }
    for (int p = tid; p < BB * (JPB / 2); p += RTHREADS) {
        int b = p >> 2, pj = p & 3;
        int j = j0 + 2 * pj;
        uint32_t w = f2h2(state[(size_t)b * HH + j], state[(size_t)b * HH + j + 1]);
        g_hf16[(size_t)(j >> 8) * CHUNK_U32 + b * 128 + (((j & 255) >> 1) ^ ((b & 7) << 2))] = w;
    }
    gridBarrier();

    const float* gatesR = g_gates;
    const float* gatesZ = g_gates + (size_t)1 * TT * BB * HH;
    const float* gatesH = g_gates + (size_t)2 * TT * BB * HH;
    const bool hasFinal = (out_size >= (int)((size_t)TT * BB * HH + BB * HH));
    float* finalOut = out + (size_t)TT * BB * HH;

    const int miA = wid & 3;
    const int niA = wid >> 2;        // 0 = r gate, 1 = z gate
    const int m0A = miA * 16;
    const int miB = wid & 3;
    const int khB = wid >> 2;        // chunks 0-1 vs 2-3

    const int jA2 = 2 * t4;
    const int bA0 = m0A + g, bA1 = bA0 + 8;
    const int jc  = j0 + jA2;
    // fp16-pair write words (cols jc, jc+1 in one word)
    const int tfW0 = (jc >> 8) * CHUNK_U32 + bA0 * 128 + (((jc & 255) >> 1) ^ gx);
    const int tfW1 = (jc >> 8) * CHUNK_U32 + bA1 * 128 + (((jc & 255) >> 1) ^ gx);

    unsigned par0 = 0, par1 = 0;

    for (int t = 0; t < TT; ++t) {
        const size_t baseT = (size_t)t * BB * HH;

        // Prefetch epilogue-A operands
        const float* gAB = (niA == 0) ? gatesR : gatesZ;
        float2 pg0 = *(const float2*)&gAB[baseT + (size_t)bA0 * HH + jc];
        float2 pg1 = *(const float2*)&gAB[baseT + (size_t)bA1 * HH + jc];
        float2 ho0 = *(const float2*)&g_h[(size_t)bA0 * HH + jc];
        float2 ho1 = *(const float2*)&g_h[(size_t)bA1 * HH + jc];

        // ================= Phase A: r and z =================
        float acc[4] = {0.f, 0.f, 0.f, 0.f};
        if (tid == 0) {
            bulkStage(sBuf[0], g_hf16, mb[0]);
            bulkStage(sBuf[1], g_hf16 + CHUNK_U32, mb[1]);
        }
        #pragma unroll 1
        for (int c = 0; c < NCH; ++c) {
            unsigned& par = (c & 1) ? par1 : par0;
            mbarWait(mb[c & 1], par & 1u);
            par++;
            const uint32_t* buf = sHg[c & 1];
            const uint2* wf = &uWf[(niA * 64 + c * 16) * 32 + lane];
            #pragma unroll
            for (int kk = 0; kk < RCHUNK / 16; ++kk) {
                int p0 = (kk * 8 + t4) ^ gx;
                int p1 = (kk * 8 + t4 + 4) ^ gx;
                uint32_t a0 = buf[bA0 * 128 + p0];
                uint32_t a1 = buf[bA1 * 128 + p0];
                uint32_t a2 = buf[bA0 * 128 + p1];
                uint32_t a3 = buf[bA1 * 128 + p1];
                uint2 b2 = wf[kk * 32];
                mma_f16(acc, a0, a1, a2, a3, b2.x, b2.y);
            }
            __syncthreads();     // all warps done with buf -> safe to re-stage
            if (c + 2 < NCH && tid == 0)
                bulkStage(sBuf[c & 1], g_hf16 + (size_t)(c + 2) * CHUNK_U32, mb[c & 1]);
        }

        // Epilogue A
        if (niA == 0) {
            float r00 = sigmoidf_(pg0.x + acc[0]);
            float r01 = sigmoidf_(pg0.y + acc[1]);
            float r10 = sigmoidf_(pg1.x + acc[2]);
            float r11 = sigmoidf_(pg1.y + acc[3]);
            g_hrf16[tfW0] = f2h2(ho0.x * r00, ho0.y * r01);
            g_hrf16[tfW1] = f2h2(ho1.x * r10, ho1.y * r11);
            *(float2*)&sHold[bA0 * JPB + jA2] = ho0;
            *(float2*)&sHold[bA1 * JPB + jA2] = ho1;
        } else {
            *(float2*)&sZ[bA0 * JPB + jA2] =
                make_float2(sigmoidf_(pg0.x + acc[0]), sigmoidf_(pg0.y + acc[1]));
            *(float2*)&sZ[bA1 * JPB + jA2] =
                make_float2(sigmoidf_(pg1.x + acc[2]), sigmoidf_(pg1.y + acc[3]));
        }

        gridBarrier();   // all h*r published

        // Prefetch candidate gates
        float2 pgh0 = *(const float2*)&gatesH[baseT + (size_t)bA0 * HH + jc];
        float2 pgh1 = *(const float2*)&gatesH[baseT + (size_t)bA1 * HH + jc];

        // ================= Phase B: candidate =================
        float accB[4] = {0.f, 0.f, 0.f, 0.f};
        if (tid == 0) {
            bulkStage(sBuf[0], g_hrf16, mb[0]);
            bulkStage(sBuf[1], g_hrf16 + CHUNK_U32, mb[1]);
        }
        #pragma unroll 1
        for (int c = 0; c < NCH; ++c) {
            unsigned& par = (c & 1) ? par1 : par0;
            mbarWait(mb[c & 1], par & 1u);
            par++;
            if ((c >> 1) == khB) {
                const uint32_t* buf = sHg[c & 1];
                const uint2* wf = &uWf[(2 * 64 + c * 16) * 32 + lane];
                const int bB0 = miB * 16 + g, bB1 = bB0 + 8;
                #pragma unroll
                for (int kk = 0; kk < RCHUNK / 16; ++kk) {
                    int p0 = (kk * 8 + t4) ^ gx;
                    int p1 = (kk * 8 + t4 + 4) ^ gx;
                    uint32_t a0 = buf[bB0 * 128 + p0];
                    uint32_t a1 = buf[bB1 * 128 + p0];
                    uint32_t a2 = buf[bB0 * 128 + p1];
                    uint32_t a3 = buf[bB1 * 128 + p1];
                    uint2 b2 = wf[kk * 32];
                    mma_f16(accB, a0, a1, a2, a3, b2.x, b2.y);
                }
            }
            __syncthreads();
            if (c + 2 < NCH && tid == 0)
                bulkStage(sBuf[c & 1], g_hrf16 + (size_t)(c + 2) * CHUNK_U32, mb[c & 1]);
        }

        if (khB == 1) {
            *(float4*)&sRed[(miB * 32 + lane) * 4] =
                make_float4(accB[0], accB[1], accB[2], accB[3]);
        }
        __syncthreads();
        if (khB == 0) {
            float4 p = *(const float4*)&sRed[(miB * 32 + lane) * 4];
            accB[0] += p.x; accB[1] += p.y; accB[2] += p.z; accB[3] += p.w;

            int b0 = miB * 16 + g, b1 = b0 + 8;
            float c00 = tanhf(pgh0.x + accB[0]);
            float c01 = tanhf(pgh0.y + accB[1]);
            float c10 = tanhf(pgh1.x + accB[2]);
            float c11 = tanhf(pgh1.y + accB[3]);
            float2 z0 = *(const float2*)&sZ[b0 * JPB + jA2];
            float2 z1 = *(const float2*)&sZ[b1 * JPB + jA2];
            float2 h0 = *(const float2*)&sHold[b0 * JPB + jA2];
            float2 h1 = *(const float2*)&sHold[b1 * JPB + jA2];
            float2 hn0 = make_float2(z0.x * h0.x + (1.f - z0.x) * c00,
                                     z0.y * h0.y + (1.f - z0.y) * c01);
            float2 hn1 = make_float2(z1.x * h1.x + (1.f - z1.x) * c10,
                                     z1.y * h1.y + (1.f - z1.y) * c11);
            *(float2*)&g_h[(size_t)b0 * HH + jc] = hn0;
            *(float2*)&g_h[(size_t)b1 * HH + jc] = hn1;
            g_hf16[tfW0] = f2h2(hn0.x, hn0.y);     // b0 == bA0, b1 == bA1
            g_hf16[tfW1] = f2h2(hn1.x, hn1.y);
            *(float2*)&out[baseT + (size_t)b0 * HH + jc] = hn0;
            *(float2*)&out[baseT + (size_t)b1 * HH + jc] = hn1;
            if (hasFinal && t == TT - 1) {
                *(float2*)&finalOut[(size_t)b0 * HH + jc] = hn0;
                *(float2*)&finalOut[(size_t)b1 * HH + jc] = hn1;
            }
        }

        gridBarrier();   // new h published
    }
}

// ---------------------------------------------------------------------------
extern "C" void kernel_launch(void* const* d_in, const int* in_sizes, int n_in,
                              void* d_out, int out_size)
{
    const float* x      = (const float*)d_in[0];
    const float* state  = (const float*)d_in[1];
    const float* w_xr_w = (const float*)d_in[2];
    const float* w_xr_b = (const float*)d_in[3];
    const float* w_hr_w = (const float*)d_in[4];
    const float* w_xz_w = (const float*)d_in[5];
    const float* w_xz_b = (const float*)d_in[6];
    const float* w_hz_w = (const float*)d_in[7];
    const float* w_xh_w = (const float*)d_in[8];
    const float* w_xh_b = (const float*)d_in[9];
    const float* w_hh_w = (const float*)d_in[10];

    cudaFuncSetAttribute(gru_recurrent,
                         cudaFuncAttributeMaxDynamicSharedMemorySize, RSMEM_BYTES);

    dim3 gg(GN / 128, GM / 128, 3);
    mma_gate<<<gg, 256>>>(x, w_xr_w, w_xz_w, w_xh_w, w_xr_b, w_xz_b, w_xh_b);

    gru_recurrent<<<NBLK, RTHREADS, RSMEM_BYTES>>>(
        state, w_hr_w, w_hz_w, w_hh_w, (float*)d_out, out_size);
}

// round 11
// speedup vs baseline: 2.1519x; 1.2121x over previous
#include <cuda_runtime.h>
#include <cuda_bf16.h>
#include <cstdint>

// Problem constants
#define TT 512
#define BB 64
#define II 1024
#define HH 1024
#define GM (TT*BB)
#define GK II
#define GN HH

// Recurrent kernel config (fp16 path)
#define NBLK 128
#define JPB  8
#define RTHREADS 256
#define RCHUNK 256               // k per chunk (fp16 -> 32KB buffer)
#define NCH (HH / RCHUNK)        // 4
#define CHUNK_U32 (BB * RCHUNK / 2)  // 8192 u32 words per chunk (fp16 pairs)

// Scratch
__device__ float    g_gates[(size_t)3 * TT * BB * HH];
__device__ float    g_h   [(size_t)BB * HH];       // fp32 h (elementwise use)
__device__ uint32_t g_hf16 [(size_t)BB * HH / 2];  // fp16-pair h, chunked+swizzled
__device__ uint32_t g_hrf16[(size_t)BB * HH / 2];  // fp16-pair h*r
__device__ unsigned g_bar_cnt;
__device__ unsigned g_bar_gen;

// fp16-pair layout: word(b,j) = (j>>8)*CHUNK_U32 + b*128 + (((j&255)>>1) ^ ((b&7)<<2))

// ---------------------------------------------------------------------------
__device__ __forceinline__ void gridBarrier() {
    __syncthreads();
    if (threadIdx.x == 0) {
        __threadfence();
        volatile unsigned* vgen = &g_bar_gen;
        unsigned gen = *vgen;
        if (atomicAdd(&g_bar_cnt, 1u) == NBLK - 1u) {
            g_bar_cnt = 0u;
            __threadfence();
            *vgen = gen + 1u;
        } else {
            while (*vgen == gen) { }
        }
        __threadfence();
    }
    __syncthreads();
}

__device__ __forceinline__ float sigmoidf_(float x) {
    return 1.0f / (1.0f + __expf(-x));
}

// pack two floats into fp16x2: low half = lo, high half = hi
__device__ __forceinline__ uint32_t f2h2(float lo, float hi) {
    uint32_t r;
    asm("cvt.rn.f16x2.f32 %0, %1, %2;" : "=r"(r) : "f"(hi), "f"(lo));
    return r;
}

__device__ __forceinline__ void mma_f16(float acc[4],
                                        uint32_t a0, uint32_t a1, uint32_t a2, uint32_t a3,
                                        uint32_t b0, uint32_t b1) {
    asm volatile(
        "mma.sync.aligned.m16n8k16.row.col.f32.f16.f16.f32 "
        "{%0,%1,%2,%3}, {%4,%5,%6,%7}, {%8,%9}, {%0,%1,%2,%3};"
        : "+f"(acc[0]), "+f"(acc[1]), "+f"(acc[2]), "+f"(acc[3])
        : "r"(a0), "r"(a1), "r"(a2), "r"(a3), "r"(b0), "r"(b1));
}

__device__ __forceinline__ void mbarInit(uint32_t mbar) {
    asm volatile("mbarrier.init.shared::cta.b64 [%0], 1;" :: "r"(mbar) : "memory");
}

__device__ __forceinline__ void bulkStage(uint32_t dst, const uint32_t* __restrict__ gsrc,
                                          uint32_t mbar) {
    asm volatile("mbarrier.arrive.expect_tx.shared::cta.b64 _, [%0], %1;"
                 :: "r"(mbar), "r"(32768u) : "memory");
    asm volatile("cp.async.bulk.shared::cta.global.mbarrier::complete_tx::bytes "
                 "[%0], [%1], %2, [%3];"
                 :: "r"(dst), "l"(gsrc), "r"(32768u), "r"(mbar) : "memory");
}

__device__ __forceinline__ void mbarWait(uint32_t mbar, uint32_t parity) {
    uint32_t done;
    do {
        asm volatile(
            "{\n\t.reg .pred p;\n\t"
            "mbarrier.try_wait.parity.acquire.cta.shared::cta.b64 p, [%1], %2;\n\t"
            "selp.b32 %0, 1, 0, p;\n\t}"
            : "=r"(done) : "r"(mbar), "r"(parity) : "memory");
    } while (!done);
}

// ---------------------------------------------------------------------------
// FP16 input projection GEMM: C[m,n] = sum_k A[m,k]*W[n,k] + bias[n].
// 128x128 CTA tile, BK=32 (2 x k16 steps). Words are fp16 pairs; word-row =
// k-pair index, u32 stride 136 (≡8 mod 32 -> frag LDS conflict-free, same
// proof as the validated R10 recurrence layout).
// ---------------------------------------------------------------------------
#define BKG 32
#define GSTR 136   // u32 stride

__global__ __launch_bounds__(256) void mma_gate(
    const float* __restrict__ A,
    const float* __restrict__ W0, const float* __restrict__ W1, const float* __restrict__ W2,
    const float* __restrict__ b0, const float* __restrict__ b1, const float* __restrict__ b2)
{
    __shared__ uint32_t As[16 * GSTR];   // 16 word-rows (k-pairs) x 128 rows
    __shared__ uint32_t Ws[16 * GSTR];

    const int gate = blockIdx.z;
    const float* W    = (gate == 0) ? W0 : (gate == 1) ? W1 : W2;
    const float* bias = (gate == 0) ? b0 : (gate == 1) ? b1 : b2;
    float* C = g_gates + (size_t)gate * GM * GN;

    const int m0 = blockIdx.y * 128;
    const int n0 = blockIdx.x * 128;
    const int tid  = threadIdx.x;
    const int wid  = tid >> 5;
    const int lane = tid & 31;
    const int g  = lane >> 2;
    const int t4 = lane & 3;

    const int wm = (wid & 1) * 64;
    const int wn = (wid >> 1) * 32;

    float acc[4][4][4];
    #pragma unroll
    for (int mi = 0; mi < 4; ++mi)
        #pragma unroll
        for (int ni = 0; ni < 4; ++ni)
            #pragma unroll
            for (int r = 0; r < 4; ++r) acc[mi][ni][r] = 0.0f;

    for (int kt = 0; kt < GK; kt += BKG) {
        // Stage: 1024 float4 each for A and W (4 per thread each).
        #pragma unroll
        for (int i = 0; i < 4; ++i) {
            int idx = tid + i * 256;          // 0..1023
            int row = idx >> 3;               // 0..127
            int kc4 = (idx & 7) * 4;          // 0,4,...,28
            int wr  = kc4 >> 1;               // word-row 0,2,...,14
            float4 a = *(const float4*)&A[(size_t)(m0 + row) * GK + kt + kc4];
            As[(wr    ) * GSTR + row] = f2h2(a.x, a.y);
            As[(wr + 1) * GSTR + row] = f2h2(a.z, a.w);
            float4 w = *(const float4*)&W[(size_t)(n0 + row) * GK + kt + kc4];
            Ws[(wr    ) * GSTR + row] = f2h2(w.x, w.y);
            Ws[(wr + 1) * GSTR + row] = f2h2(w.z, w.w);
        }
        __syncthreads();

        #pragma unroll
        for (int ks = 0; ks < 2; ++ks) {      // two k16 steps per BK=32
            const int wr = ks * 8;
            uint32_t af[4][4];
            #pragma unroll
            for (int mi = 0; mi < 4; ++mi) {
                int m = wm + mi * 16 + g;
                af[mi][0] = As[(wr + t4    ) * GSTR + m    ];
                af[mi][1] = As[(wr + t4    ) * GSTR + m + 8];
                af[mi][2] = As[(wr + t4 + 4) * GSTR + m    ];
                af[mi][3] = As[(wr + t4 + 4) * GSTR + m + 8];
            }
            uint32_t bf[4][2];
            #pragma unroll
            for (int ni = 0; ni < 4; ++ni) {
                int n = wn + ni * 8 + g;
                bf[ni][0] = Ws[(wr + t4    ) * GSTR + n];
                bf[ni][1] = Ws[(wr + t4 + 4) * GSTR + n];
            }
            #pragma unroll
            for (int mi = 0; mi < 4; ++mi)
                #pragma unroll
                for (int ni = 0; ni < 4; ++ni)
                    mma_f16(acc[mi][ni], af[mi][0], af[mi][1], af[mi][2], af[mi][3],
                            bf[ni][0], bf[ni][1]);
        }
        __syncthreads();
    }

    #pragma unroll
    for (int mi = 0; mi < 4; ++mi) {
        int mrow = m0 + wm + mi * 16 + g;
        #pragma unroll
        for (int ni = 0; ni < 4; ++ni) {
            int col = n0 + wn + ni * 8 + 2 * t4;
            float bx = bias[col], by = bias[col + 1];
            float2 o0 = make_float2(acc[mi][ni][0] + bx, acc[mi][ni][1] + by);
            float2 o1 = make_float2(acc[mi][ni][2] + bx, acc[mi][ni][3] + by);
            *(float2*)&C[(size_t)mrow * GN + col] = o0;
            *(float2*)&C[(size_t)(mrow + 8) * GN + col] = o1;
        }
    }
}

// ---------------------------------------------------------------------------
// R10 recurrent kernel (unchanged): fp16 m16n8k16 MMA, fp16-pair bulk-staged
// h, 256-k chunks, spin gridBarrier.
// ---------------------------------------------------------------------------
#define OFF_WF   0
#define SZ_WF    (3 * 64 * 32 * 8)                  // 49152 (fp16 weight frags)
#define OFF_SB0  (OFF_WF + SZ_WF)                   // 32KB buffer 0
#define OFF_SB1  (OFF_SB0 + 32768)
#define OFF_MBAR (OFF_SB1 + 32768)                  // 2 mbarriers
#define OFF_SZ   (OFF_MBAR + 16)
#define SZ_SZ    (BB * JPB * 4)
#define OFF_SHO  (OFF_SZ + SZ_SZ)
#define OFF_SRED (OFF_SHO + SZ_SZ)
#define SZ_SRED  (4 * 32 * 4 * 4)
#define RSMEM_BYTES (OFF_SRED + SZ_SRED)            // ~121KB

__global__ __launch_bounds__(RTHREADS, 1) void gru_recurrent(
    const float* __restrict__ state,
    const float* __restrict__ w_hr,
    const float* __restrict__ w_hz,
    const float* __restrict__ w_hh,
    float* __restrict__ out,
    int out_size)
{
    extern __shared__ char smem[];
    uint2*    uWf  = (uint2*)(smem + OFF_WF);       // [g3][kk16][lane] fp16 B-frags
    uint32_t* sHg[2];
    sHg[0] = (uint32_t*)(smem + OFF_SB0);
    sHg[1] = (uint32_t*)(smem + OFF_SB1);
    float*    sZ    = (float*)(smem + OFF_SZ);
    float*    sHold = (float*)(smem + OFF_SHO);
    float*    sRed  = (float*)(smem + OFF_SRED);

    uint32_t sBuf[2], mb[2];
    sBuf[0] = (uint32_t)__cvta_generic_to_shared(sHg[0]);
    sBuf[1] = (uint32_t)__cvta_generic_to_shared(sHg[1]);
    mb[0] = (uint32_t)__cvta_generic_to_shared(smem + OFF_MBAR);
    mb[1] = mb[0] + 8;

    const int j0  = blockIdx.x * JPB;
    const int tid = threadIdx.x;
    const int wid = tid >> 5;
    const int lane = tid & 31;
    const int g  = lane >> 2;
    const int t4 = lane & 3;
    const int gx = g << 2;           // XOR swizzle key

    if (tid == 0) { mbarInit(mb[0]); mbarInit(mb[1]); }

    // ---- weights -> fp16 B-fragment order (once) ----
    {
        const float* Ws3[3] = {w_hr, w_hz, w_hh};
        for (int g3 = 0; g3 < 3; ++g3) {
            const float* W = Ws3[g3];
            for (int idx = tid; idx < 64 * 32; idx += RTHREADS) {
                int kk  = idx >> 5;
                int ln  = idx & 31;
                int jj  = ln >> 2;
                int k0  = (kk << 4) + ((ln & 3) << 1);
                const float* Wr = &W[(size_t)(j0 + jj) * HH];
                uint2 v;
                v.x = f2h2(Wr[k0],     Wr[k0 + 1]);
                v.y = f2h2(Wr[k0 + 8], Wr[k0 + 9]);
                uWf[(g3 * 64 + kk) * 32 + ln] = v;
            }
        }
    }

    // ---- init h (fp32 + fp16-pair swizzled) for my columns ----
    for (int p = tid; p < BB * JPB; p += RTHREADS) {
        int b = p >> 3, jj = p & 7;
        int j = j0 + jj;
        g_h[(size_t)b * HH + j] = state[(size_t)b * HH + j];
    }
    for (int p = tid; p < BB * (JPB / 2); p += RTHREADS) {
        int b = p >> 2, pj = p & 3;
        int j = j0 + 2 * pj;
        uint32_t w = f2h2(state[(size_t)b * HH + j], state[(size_t)b * HH + j + 1]);
        g_hf16[(size_t)(j >> 8) * CHUNK_U32 + b * 128 + (((j & 255) >> 1) ^ ((b & 7) << 2))] = w;
    }
    gridBarrier();

    const float* gatesR = g_gates;
    const float* gatesZ = g_gates + (size_t)1 * TT * BB * HH;
    const float* gatesH = g_gates + (size_t)2 * TT * BB * HH;
    const bool hasFinal = (out_size >= (int)((size_t)TT * BB * HH + BB * HH));
    float* finalOut = out + (size_t)TT * BB * HH;

    const int miA = wid & 3;
    const int niA = wid >> 2;        // 0 = r gate, 1 = z gate
    const int m0A = miA * 16;
    const int miB = wid & 3;
    const int khB = wid >> 2;        // chunks 0-1 vs 2-3

    const int jA2 = 2 * t4;
    const int bA0 = m0A + g, bA1 = bA0 + 8;
    const int jc  = j0 + jA2;
    const int tfW0 = (jc >> 8) * CHUNK_U32 + bA0 * 128 + (((jc & 255) >> 1) ^ gx);
    const int tfW1 = (jc >> 8) * CHUNK_U32 + bA1 * 128 + (((jc & 255) >> 1) ^ gx);

    unsigned par0 = 0, par1 = 0;

    for (int t = 0; t < TT; ++t) {
        const size_t baseT = (size_t)t * BB * HH;

        const float* gAB = (niA == 0) ? gatesR : gatesZ;
        float2 pg0 = *(const float2*)&gAB[baseT + (size_t)bA0 * HH + jc];
        float2 pg1 = *(const float2*)&gAB[baseT + (size_t)bA1 * HH + jc];
        float2 ho0 = *(const float2*)&g_h[(size_t)bA0 * HH + jc];
        float2 ho1 = *(const float2*)&g_h[(size_t)bA1 * HH + jc];

        // ================= Phase A: r and z =================
        float acc[4] = {0.f, 0.f, 0.f, 0.f};
        if (tid == 0) {
            bulkStage(sBuf[0], g_hf16, mb[0]);
            bulkStage(sBuf[1], g_hf16 + CHUNK_U32, mb[1]);
        }
        #pragma unroll 1
        for (int c = 0; c < NCH; ++c) {
            unsigned& par = (c & 1) ? par1 : par0;
            mbarWait(mb[c & 1], par & 1u);
            par++;
            const uint32_t* buf = sHg[c & 1];
            const uint2* wf = &uWf[(niA * 64 + c * 16) * 32 + lane];
            #pragma unroll
            for (int kk = 0; kk < RCHUNK / 16; ++kk) {
                int p0 = (kk * 8 + t4) ^ gx;
                int p1 = (kk * 8 + t4 + 4) ^ gx;
                uint32_t a0 = buf[bA0 * 128 + p0];
                uint32_t a1 = buf[bA1 * 128 + p0];
                uint32_t a2 = buf[bA0 * 128 + p1];
                uint32_t a3 = buf[bA1 * 128 + p1];
                uint2 b2 = wf[kk * 32];
                mma_f16(acc, a0, a1, a2, a3, b2.x, b2.y);
            }
            __syncthreads();
            if (c + 2 < NCH && tid == 0)
                bulkStage(sBuf[c & 1], g_hf16 + (size_t)(c + 2) * CHUNK_U32, mb[c & 1]);
        }

        // Epilogue A
        if (niA == 0) {
            float r00 = sigmoidf_(pg0.x + acc[0]);
            float r01 = sigmoidf_(pg0.y + acc[1]);
            float r10 = sigmoidf_(pg1.x + acc[2]);
            float r11 = sigmoidf_(pg1.y + acc[3]);
            g_hrf16[tfW0] = f2h2(ho0.x * r00, ho0.y * r01);
            g_hrf16[tfW1] = f2h2(ho1.x * r10, ho1.y * r11);
            *(float2*)&sHold[bA0 * JPB + jA2] = ho0;
            *(float2*)&sHold[bA1 * JPB + jA2] = ho1;
        } else {
            *(float2*)&sZ[bA0 * JPB + jA2] =
                make_float2(sigmoidf_(pg0.x + acc[0]), sigmoidf_(pg0.y + acc[1]));
            *(float2*)&sZ[bA1 * JPB + jA2] =
                make_float2(sigmoidf_(pg1.x + acc[2]), sigmoidf_(pg1.y + acc[3]));
        }

        gridBarrier();   // all h*r published

        float2 pgh0 = *(const float2*)&gatesH[baseT + (size_t)bA0 * HH + jc];
        float2 pgh1 = *(const float2*)&gatesH[baseT + (size_t)bA1 * HH + jc];

        // ================= Phase B: candidate =================
        float accB[4] = {0.f, 0.f, 0.f, 0.f};
        if (tid == 0) {
            bulkStage(sBuf[0], g_hrf16, mb[0]);
            bulkStage(sBuf[1], g_hrf16 + CHUNK_U32, mb[1]);
        }
        #pragma unroll 1
        for (int c = 0; c < NCH; ++c) {
            unsigned& par = (c & 1) ? par1 : par0;
            mbarWait(mb[c & 1], par & 1u);
            par++;
            if ((c >> 1) == khB) {
                const uint32_t* buf = sHg[c & 1];
                const uint2* wf = &uWf[(2 * 64 + c * 16) * 32 + lane];
                const int bB0 = miB * 16 + g, bB1 = bB0 + 8;
                #pragma unroll
                for (int kk = 0; kk < RCHUNK / 16; ++kk) {
                    int p0 = (kk * 8 + t4) ^ gx;
                    int p1 = (kk * 8 + t4 + 4) ^ gx;
                    uint32_t a0 = buf[bB0 * 128 + p0];
                    uint32_t a1 = buf[bB1 * 128 + p0];
                    uint32_t a2 = buf[bB0 * 128 + p1];
                    uint32_t a3 = buf[bB1 * 128 + p1];
                    uint2 b2 = wf[kk * 32];
                    mma_f16(accB, a0, a1, a2, a3, b2.x, b2.y);
                }
            }
            __syncthreads();
            if (c + 2 < NCH && tid == 0)
                bulkStage(sBuf[c & 1], g_hrf16 + (size_t)(c + 2) * CHUNK_U32, mb[c & 1]);
        }

        if (khB == 1) {
            *(float4*)&sRed[(miB * 32 + lane) * 4] =
                make_float4(accB[0], accB[1], accB[2], accB[3]);
        }
        __syncthreads();
        if (khB == 0) {
            float4 p = *(const float4*)&sRed[(miB * 32 + lane) * 4];
            accB[0] += p.x; accB[1] += p.y; accB[2] += p.z; accB[3] += p.w;

            int b0 = miB * 16 + g, b1 = b0 + 8;
            float c00 = tanhf(pgh0.x + accB[0]);
            float c01 = tanhf(pgh0.y + accB[1]);
            float c10 = tanhf(pgh1.x + accB[2]);
            float c11 = tanhf(pgh1.y + accB[3]);
            float2 z0 = *(const float2*)&sZ[b0 * JPB + jA2];
            float2 z1 = *(const float2*)&sZ[b1 * JPB + jA2];
            float2 h0 = *(const float2*)&sHold[b0 * JPB + jA2];
            float2 h1 = *(const float2*)&sHold[b1 * JPB + jA2];
            float2 hn0 = make_float2(z0.x * h0.x + (1.f - z0.x) * c00,
                                     z0.y * h0.y + (1.f - z0.y) * c01);
            float2 hn1 = make_float2(z1.x * h1.x + (1.f - z1.x) * c10,
                                     z1.y * h1.y + (1.f - z1.y) * c11);
            *(float2*)&g_h[(size_t)b0 * HH + jc] = hn0;
            *(float2*)&g_h[(size_t)b1 * HH + jc] = hn1;
            g_hf16[tfW0] = f2h2(hn0.x, hn0.y);
            g_hf16[tfW1] = f2h2(hn1.x, hn1.y);
            *(float2*)&out[baseT + (size_t)b0 * HH + jc] = hn0;
            *(float2*)&out[baseT + (size_t)b1 * HH + jc] = hn1;
            if (hasFinal && t == TT - 1) {
                *(float2*)&finalOut[(size_t)b0 * HH + jc] = hn0;
                *(float2*)&finalOut[(size_t)b1 * HH + jc] = hn1;
            }
        }

        gridBarrier();   // new h published
    }
}

// ---------------------------------------------------------------------------
extern "C" void kernel_launch(void* const* d_in, const int* in_sizes, int n_in,
                              void* d_out, int out_size)
{
    const float* x      = (const float*)d_in[0];
    const float* state  = (const float*)d_in[1];
    const float* w_xr_w = (const float*)d_in[2];
    const float* w_xr_b = (const float*)d_in[3];
    const float* w_hr_w = (const float*)d_in[4];
    const float* w_xz_w = (const float*)d_in[5];
    const float* w_xz_b = (const float*)d_in[6];
    const float* w_hz_w = (const float*)d_in[7];
    const float* w_xh_w = (const float*)d_in[8];
    const float* w_xh_b = (const float*)d_in[9];
    const float* w_hh_w = (const float*)d_in[10];

    cudaFuncSetAttribute(gru_recurrent,
                         cudaFuncAttributeMaxDynamicSharedMemorySize, RSMEM_BYTES);

    dim3 gg(GN / 128, GM / 128, 3);
    mma_gate<<<gg, 256>>>(x, w_xr_w, w_xz_w, w_xh_w, w_xr_b, w_xz_b, w_xh_b);

    gru_recurrent<<<NBLK, RTHREADS, RSMEM_BYTES>>>(
        state, w_hr_w, w_hz_w, w_hh_w, (float*)d_out, out_size);
}

// round 12
// speedup vs baseline: 2.3688x; 1.1008x over previous
#include <cuda_runtime.h>
#include <cuda_bf16.h>
#include <cstdint>

// Problem constants
#define TT 512
#define BB 64
#define II 1024
#define HH 1024
#define GM (TT*BB)
#define GK II
#define GN HH

// Recurrent kernel config (fp16 path)
#define NBLK 128
#define JPB  8
#define RTHREADS 256
#define RCHUNK 256               // k per chunk (fp16 -> 32KB buffer)
#define NCH (HH / RCHUNK)        // 4
#define CHUNK_U32 (BB * RCHUNK / 2)  // 8192 u32 words per chunk (fp16 pairs)

// Scratch
__device__ float    g_gates[(size_t)3 * TT * BB * HH];
__device__ float    g_h   [(size_t)BB * HH];       // fp32 h (elementwise use)
__device__ uint32_t g_hf16 [(size_t)BB * HH / 2];  // fp16-pair h, chunked+swizzled
__device__ uint32_t g_hrf16[(size_t)BB * HH / 2];  // fp16-pair h*r
__device__ unsigned g_bar_cnt;
__device__ unsigned g_bar_gen;

// fp16-pair layout: word(b,j) = (j>>8)*CHUNK_U32 + b*128 + (((j&255)>>1) ^ ((b&7)<<2))

// ---------------------------------------------------------------------------
__device__ __forceinline__ void gridBarrier() {
    __syncthreads();
    if (threadIdx.x == 0) {
        __threadfence();
        volatile unsigned* vgen = &g_bar_gen;
        unsigned gen = *vgen;
        if (atomicAdd(&g_bar_cnt, 1u) == NBLK - 1u) {
            g_bar_cnt = 0u;
            __threadfence();
            *vgen = gen + 1u;
        } else {
            while (*vgen == gen) { }
        }
        __threadfence();
    }
    __syncthreads();
}

__device__ __forceinline__ float sigmoidf_(float x) {
    return 1.0f / (1.0f + __expf(-x));
}

// pack two floats into fp16x2: low half = lo, high half = hi
__device__ __forceinline__ uint32_t f2h2(float lo, float hi) {
    uint32_t r;
    asm("cvt.rn.f16x2.f32 %0, %1, %2;" : "=r"(r) : "f"(hi), "f"(lo));
    return r;
}

__device__ __forceinline__ void mma_f16(float acc[4],
                                        uint32_t a0, uint32_t a1, uint32_t a2, uint32_t a3,
                                        uint32_t b0, uint32_t b1) {
    asm volatile(
        "mma.sync.aligned.m16n8k16.row.col.f32.f16.f16.f32 "
        "{%0,%1,%2,%3}, {%4,%5,%6,%7}, {%8,%9}, {%0,%1,%2,%3};"
        : "+f"(acc[0]), "+f"(acc[1]), "+f"(acc[2]), "+f"(acc[3])
        : "r"(a0), "r"(a1), "r"(a2), "r"(a3), "r"(b0), "r"(b1));
}

__device__ __forceinline__ void mbarInit(uint32_t mbar) {
    asm volatile("mbarrier.init.shared::cta.b64 [%0], 1;" :: "r"(mbar) : "memory");
}

__device__ __forceinline__ void bulkStage(uint32_t dst, const uint32_t* __restrict__ gsrc,
                                          uint32_t mbar) {
    asm volatile("mbarrier.arrive.expect_tx.shared::cta.b64 _, [%0], %1;"
                 :: "r"(mbar), "r"(32768u) : "memory");
    asm volatile("cp.async.bulk.shared::cta.global.mbarrier::complete_tx::bytes "
                 "[%0], [%1], %2, [%3];"
                 :: "r"(dst), "l"(gsrc), "r"(32768u), "r"(mbar) : "memory");
}

__device__ __forceinline__ void mbarWait(uint32_t mbar, uint32_t parity) {
    uint32_t done;
    do {
        asm volatile(
            "{\n\t.reg .pred p;\n\t"
            "mbarrier.try_wait.parity.acquire.cta.shared::cta.b64 p, [%1], %2;\n\t"
            "selp.b32 %0, 1, 0, p;\n\t}"
            : "=r"(done) : "r"(mbar), "r"(parity) : "memory");
    } while (!done);
}

// ---------------------------------------------------------------------------
// FP16 input projection GEMM (unchanged from R11, ~0.6ms)
// ---------------------------------------------------------------------------
#define BKG 32
#define GSTR 136   // u32 stride

__global__ __launch_bounds__(256) void mma_gate(
    const float* __restrict__ A,
    const float* __restrict__ W0, const float* __restrict__ W1, const float* __restrict__ W2,
    const float* __restrict__ b0, const float* __restrict__ b1, const float* __restrict__ b2)
{
    __shared__ uint32_t As[16 * GSTR];
    __shared__ uint32_t Ws[16 * GSTR];

    const int gate = blockIdx.z;
    const float* W    = (gate == 0) ? W0 : (gate == 1) ? W1 : W2;
    const float* bias = (gate == 0) ? b0 : (gate == 1) ? b1 : b2;
    float* C = g_gates + (size_t)gate * GM * GN;

    const int m0 = blockIdx.y * 128;
    const int n0 = blockIdx.x * 128;
    const int tid  = threadIdx.x;
    const int wid  = tid >> 5;
    const int lane = tid & 31;
    const int g  = lane >> 2;
    const int t4 = lane & 3;

    const int wm = (wid & 1) * 64;
    const int wn = (wid >> 1) * 32;

    float acc[4][4][4];
    #pragma unroll
    for (int mi = 0; mi < 4; ++mi)
        #pragma unroll
        for (int ni = 0; ni < 4; ++ni)
            #pragma unroll
            for (int r = 0; r < 4; ++r) acc[mi][ni][r] = 0.0f;

    for (int kt = 0; kt < GK; kt += BKG) {
        #pragma unroll
        for (int i = 0; i < 4; ++i) {
            int idx = tid + i * 256;
            int row = idx >> 3;
            int kc4 = (idx & 7) * 4;
            int wr  = kc4 >> 1;
            float4 a = *(const float4*)&A[(size_t)(m0 + row) * GK + kt + kc4];
            As[(wr    ) * GSTR + row] = f2h2(a.x, a.y);
            As[(wr + 1) * GSTR + row] = f2h2(a.z, a.w);
            float4 w = *(const float4*)&W[(size_t)(n0 + row) * GK + kt + kc4];
            Ws[(wr    ) * GSTR + row] = f2h2(w.x, w.y);
            Ws[(wr + 1) * GSTR + row] = f2h2(w.z, w.w);
        }
        __syncthreads();

        #pragma unroll
        for (int ks = 0; ks < 2; ++ks) {
            const int wr = ks * 8;
            uint32_t af[4][4];
            #pragma unroll
            for (int mi = 0; mi < 4; ++mi) {
                int m = wm + mi * 16 + g;
                af[mi][0] = As[(wr + t4    ) * GSTR + m    ];
                af[mi][1] = As[(wr + t4    ) * GSTR + m + 8];
                af[mi][2] = As[(wr + t4 + 4) * GSTR + m    ];
                af[mi][3] = As[(wr + t4 + 4) * GSTR + m + 8];
            }
            uint32_t bf[4][2];
            #pragma unroll
            for (int ni = 0; ni < 4; ++ni) {
                int n = wn + ni * 8 + g;
                bf[ni][0] = Ws[(wr + t4    ) * GSTR + n];
                bf[ni][1] = Ws[(wr + t4 + 4) * GSTR + n];
            }
            #pragma unroll
            for (int mi = 0; mi < 4; ++mi)
                #pragma unroll
                for (int ni = 0; ni < 4; ++ni)
                    mma_f16(acc[mi][ni], af[mi][0], af[mi][1], af[mi][2], af[mi][3],
                            bf[ni][0], bf[ni][1]);
        }
        __syncthreads();
    }

    #pragma unroll
    for (int mi = 0; mi < 4; ++mi) {
        int mrow = m0 + wm + mi * 16 + g;
        #pragma unroll
        for (int ni = 0; ni < 4; ++ni) {
            int col = n0 + wn + ni * 8 + 2 * t4;
            float bx = bias[col], by = bias[col + 1];
            float2 o0 = make_float2(acc[mi][ni][0] + bx, acc[mi][ni][1] + by);
            float2 o1 = make_float2(acc[mi][ni][2] + bx, acc[mi][ni][3] + by);
            *(float2*)&C[(size_t)mrow * GN + col] = o0;
            *(float2*)&C[(size_t)(mrow + 8) * GN + col] = o1;
        }
    }
}

// ---------------------------------------------------------------------------
// R12 recurrent kernel: 4 RESIDENT chunk buffers (no recycling) -> zero
// intra-phase __syncthreads; constant mbar parity (A=0, B=1); 2-way
// accumulator interleave. gridBarrier protects cross-phase buffer reuse.
// ---------------------------------------------------------------------------
#define OFF_WF   0
#define SZ_WF    (3 * 64 * 32 * 8)                  // 49152
#define SZ_SB    32768
#define OFF_SB0  (OFF_WF + SZ_WF)                   // 4 x 32KB buffers
#define OFF_MBAR (OFF_SB0 + 4 * SZ_SB)              // 4 mbarriers (32 B)
#define OFF_SZ   (OFF_MBAR + 32)
#define SZ_SZ    (BB * JPB * 4)
#define OFF_SHO  (OFF_SZ + SZ_SZ)
#define OFF_SRED (OFF_SHO + SZ_SZ)
#define SZ_SRED  (4 * 32 * 4 * 4)
#define RSMEM_BYTES (OFF_SRED + SZ_SRED)            // ~182KB

__global__ __launch_bounds__(RTHREADS, 1) void gru_recurrent(
    const float* __restrict__ state,
    const float* __restrict__ w_hr,
    const float* __restrict__ w_hz,
    const float* __restrict__ w_hh,
    float* __restrict__ out,
    int out_size)
{
    extern __shared__ char smem[];
    uint2*    uWf  = (uint2*)(smem + OFF_WF);
    float*    sZ    = (float*)(smem + OFF_SZ);
    float*    sHold = (float*)(smem + OFF_SHO);
    float*    sRed  = (float*)(smem + OFF_SRED);

    const uint32_t smemBase = (uint32_t)__cvta_generic_to_shared(smem);
    uint32_t sBuf[4], mb[4];
    #pragma unroll
    for (int c = 0; c < 4; ++c) {
        sBuf[c] = smemBase + OFF_SB0 + c * SZ_SB;
        mb[c]   = smemBase + OFF_MBAR + c * 8;
    }
    const uint32_t* sHg[4];
    #pragma unroll
    for (int c = 0; c < 4; ++c)
        sHg[c] = (const uint32_t*)(smem + OFF_SB0 + c * SZ_SB);

    const int j0  = blockIdx.x * JPB;
    const int tid = threadIdx.x;
    const int wid = tid >> 5;
    const int lane = tid & 31;
    const int g  = lane >> 2;
    const int t4 = lane & 3;
    const int gx = g << 2;           // XOR swizzle key

    if (tid == 0) {
        #pragma unroll
        for (int c = 0; c < 4; ++c) mbarInit(mb[c]);
    }

    // ---- weights -> fp16 B-fragment order (once) ----
    {
        const float* Ws3[3] = {w_hr, w_hz, w_hh};
        for (int g3 = 0; g3 < 3; ++g3) {
            const float* W = Ws3[g3];
            for (int idx = tid; idx < 64 * 32; idx += RTHREADS) {
                int kk  = idx >> 5;
                int ln  = idx & 31;
                int jj  = ln >> 2;
                int k0  = (kk << 4) + ((ln & 3) << 1);
                const float* Wr = &W[(size_t)(j0 + jj) * HH];
                uint2 v;
                v.x = f2h2(Wr[k0],     Wr[k0 + 1]);
                v.y = f2h2(Wr[k0 + 8], Wr[k0 + 9]);
                uWf[(g3 * 64 + kk) * 32 + ln] = v;
            }
        }
    }

    // ---- init h (fp32 + fp16-pair swizzled) for my columns ----
    for (int p = tid; p < BB * JPB; p += RTHREADS) {
        int b = p >> 3, jj = p & 7;
        int j = j0 + jj;
        g_h[(size_t)b * HH + j] = state[(size_t)b * HH + j];
    }
    for (int p = tid; p < BB * (JPB / 2); p += RTHREADS) {
        int b = p >> 2, pj = p & 3;
        int j = j0 + 2 * pj;
        uint32_t w = f2h2(state[(size_t)b * HH + j], state[(size_t)b * HH + j + 1]);
        g_hf16[(size_t)(j >> 8) * CHUNK_U32 + b * 128 + (((j & 255) >> 1) ^ ((b & 7) << 2))] = w;
    }
    gridBarrier();   // h + weights + mbars ready everywhere

    const float* gatesR = g_gates;
    const float* gatesZ = g_gates + (size_t)1 * TT * BB * HH;
    const float* gatesH = g_gates + (size_t)2 * TT * BB * HH;
    const bool hasFinal = (out_size >= (int)((size_t)TT * BB * HH + BB * HH));
    float* finalOut = out + (size_t)TT * BB * HH;

    const int miA = wid & 3;
    const int niA = wid >> 2;        // 0 = r gate, 1 = z gate
    const int m0A = miA * 16;
    const int miB = wid & 3;
    const int khB = wid >> 2;        // chunks 0-1 vs 2-3

    const int jA2 = 2 * t4;
    const int bA0 = m0A + g, bA1 = bA0 + 8;
    const int jc  = j0 + jA2;
    const int tfW0 = (jc >> 8) * CHUNK_U32 + bA0 * 128 + (((jc & 255) >> 1) ^ gx);
    const int tfW1 = (jc >> 8) * CHUNK_U32 + bA1 * 128 + (((jc & 255) >> 1) ^ gx);

    for (int t = 0; t < TT; ++t) {
        const size_t baseT = (size_t)t * BB * HH;

        const float* gAB = (niA == 0) ? gatesR : gatesZ;
        float2 pg0 = *(const float2*)&gAB[baseT + (size_t)bA0 * HH + jc];
        float2 pg1 = *(const float2*)&gAB[baseT + (size_t)bA1 * HH + jc];
        float2 ho0 = *(const float2*)&g_h[(size_t)bA0 * HH + jc];
        float2 ho1 = *(const float2*)&g_h[(size_t)bA1 * HH + jc];

        // ================= Phase A: r and z (mbar parity 0) =================
        float ac0[4] = {0.f, 0.f, 0.f, 0.f};
        float ac1[4] = {0.f, 0.f, 0.f, 0.f};
        if (tid == 0) {
            #pragma unroll
            for (int c = 0; c < NCH; ++c)
                bulkStage(sBuf[c], g_hf16 + (size_t)c * CHUNK_U32, mb[c]);
        }
        #pragma unroll
        for (int c = 0; c < NCH; ++c) {
            mbarWait(mb[c], 0u);
            const uint32_t* buf = sHg[c];
            const uint2* wf = &uWf[(niA * 64 + c * 16) * 32 + lane];
            #pragma unroll
            for (int kk = 0; kk < RCHUNK / 16; ++kk) {
                int p0 = (kk * 8 + t4) ^ gx;
                int p1 = (kk * 8 + t4 + 4) ^ gx;
                uint32_t a0 = buf[bA0 * 128 + p0];
                uint32_t a1 = buf[bA1 * 128 + p0];
                uint32_t a2 = buf[bA0 * 128 + p1];
                uint32_t a3 = buf[bA1 * 128 + p1];
                uint2 b2 = wf[kk * 32];
                mma_f16((kk & 1) ? ac1 : ac0, a0, a1, a2, a3, b2.x, b2.y);
            }
        }
        float aS0 = ac0[0] + ac1[0];
        float aS1 = ac0[1] + ac1[1];
        float aS2 = ac0[2] + ac1[2];
        float aS3 = ac0[3] + ac1[3];

        // Epilogue A
        if (niA == 0) {
            float r00 = sigmoidf_(pg0.x + aS0);
            float r01 = sigmoidf_(pg0.y + aS1);
            float r10 = sigmoidf_(pg1.x + aS2);
            float r11 = sigmoidf_(pg1.y + aS3);
            g_hrf16[tfW0] = f2h2(ho0.x * r00, ho0.y * r01);
            g_hrf16[tfW1] = f2h2(ho1.x * r10, ho1.y * r11);
            *(float2*)&sHold[bA0 * JPB + jA2] = ho0;
            *(float2*)&sHold[bA1 * JPB + jA2] = ho1;
        } else {
            *(float2*)&sZ[bA0 * JPB + jA2] =
                make_float2(sigmoidf_(pg0.x + aS0), sigmoidf_(pg0.y + aS1));
            *(float2*)&sZ[bA1 * JPB + jA2] =
                make_float2(sigmoidf_(pg1.x + aS2), sigmoidf_(pg1.y + aS3));
        }

        gridBarrier();   // all h*r published; all phase-A buffer reads done

        float2 pgh0 = *(const float2*)&gatesH[baseT + (size_t)bA0 * HH + jc];
        float2 pgh1 = *(const float2*)&gatesH[baseT + (size_t)bA1 * HH + jc];

        // ================= Phase B: candidate (mbar parity 1) =================
        float bc0[4] = {0.f, 0.f, 0.f, 0.f};
        float bc1[4] = {0.f, 0.f, 0.f, 0.f};
        if (tid == 0) {
            #pragma unroll
            for (int c = 0; c < NCH; ++c)
                bulkStage(sBuf[c], g_hrf16 + (size_t)c * CHUNK_U32, mb[c]);
        }
        {
            const int bB0 = miB * 16 + g, bB1 = bB0 + 8;
            #pragma unroll
            for (int ci = 0; ci < 2; ++ci) {
                int c = khB * 2 + ci;
                mbarWait(mb[c], 1u);
                const uint32_t* buf = sHg[c];
                const uint2* wf = &uWf[(2 * 64 + c * 16) * 32 + lane];
                #pragma unroll
                for (int kk = 0; kk < RCHUNK / 16; ++kk) {
                    int p0 = (kk * 8 + t4) ^ gx;
                    int p1 = (kk * 8 + t4 + 4) ^ gx;
                    uint32_t a0 = buf[bB0 * 128 + p0];
                    uint32_t a1 = buf[bB1 * 128 + p0];
                    uint32_t a2 = buf[bB0 * 128 + p1];
                    uint32_t a3 = buf[bB1 * 128 + p1];
                    uint2 b2 = wf[kk * 32];
                    mma_f16((kk & 1) ? bc1 : bc0, a0, a1, a2, a3, b2.x, b2.y);
                }
            }
        }
        float bS0 = bc0[0] + bc1[0];
        float bS1 = bc0[1] + bc1[1];
        float bS2 = bc0[2] + bc1[2];
        float bS3 = bc0[3] + bc1[3];

        if (khB == 1) {
            *(float4*)&sRed[(miB * 32 + lane) * 4] = make_float4(bS0, bS1, bS2, bS3);
        }
        __syncthreads();
        if (khB == 0) {
            float4 p = *(const float4*)&sRed[(miB * 32 + lane) * 4];
            bS0 += p.x; bS1 += p.y; bS2 += p.z; bS3 += p.w;

            int b0 = miB * 16 + g, b1 = b0 + 8;
            float c00 = tanhf(pgh0.x + bS0);
            float c01 = tanhf(pgh0.y + bS1);
            float c10 = tanhf(pgh1.x + bS2);
            float c11 = tanhf(pgh1.y + bS3);
            float2 z0 = *(const float2*)&sZ[b0 * JPB + jA2];
            float2 z1 = *(const float2*)&sZ[b1 * JPB + jA2];
            float2 h0 = *(const float2*)&sHold[b0 * JPB + jA2];
            float2 h1 = *(const float2*)&sHold[b1 * JPB + jA2];
            float2 hn0 = make_float2(z0.x * h0.x + (1.f - z0.x) * c00,
                                     z0.y * h0.y + (1.f - z0.y) * c01);
            float2 hn1 = make_float2(z1.x * h1.x + (1.f - z1.x) * c10,
                                     z1.y * h1.y + (1.f - z1.y) * c11);
            *(float2*)&g_h[(size_t)b0 * HH + jc] = hn0;
            *(float2*)&g_h[(size_t)b1 * HH + jc] = hn1;
            g_hf16[tfW0] = f2h2(hn0.x, hn0.y);
            g_hf16[tfW1] = f2h2(hn1.x, hn1.y);
            *(float2*)&out[baseT + (size_t)b0 * HH + jc] = hn0;
            *(float2*)&out[baseT + (size_t)b1 * HH + jc] = hn1;
            if (hasFinal && t == TT - 1) {
                *(float2*)&finalOut[(size_t)b0 * HH + jc] = hn0;
                *(float2*)&finalOut[(size_t)b1 * HH + jc] = hn1;
            }
        }

        gridBarrier();   // new h published; all phase-B buffer reads done
    }
}

// ---------------------------------------------------------------------------
extern "C" void kernel_launch(void* const* d_in, const int* in_sizes, int n_in,
                              void* d_out, int out_size)
{
    const float* x      = (const float*)d_in[0];
    const float* state  = (const float*)d_in[1];
    const float* w_xr_w = (const float*)d_in[2];
    const float* w_xr_b = (const float*)d_in[3];
    const float* w_hr_w = (const float*)d_in[4];
    const float* w_xz_w = (const float*)d_in[5];
    const float* w_xz_b = (const float*)d_in[6];
    const float* w_hz_w = (const float*)d_in[7];
    const float* w_xh_w = (const float*)d_in[8];
    const float* w_xh_b = (const float*)d_in[9];
    const float* w_hh_w = (const float*)d_in[10];

    cudaFuncSetAttribute(gru_recurrent,
                         cudaFuncAttributeMaxDynamicSharedMemorySize, RSMEM_BYTES);

    dim3 gg(GN / 128, GM / 128, 3);
    mma_gate<<<gg, 256>>>(x, w_xr_w, w_xz_w, w_xh_w, w_xr_b, w_xz_b, w_xh_b);

    gru_recurrent<<<NBLK, RTHREADS, RSMEM_BYTES>>>(
        state, w_hr_w, w_hz_w, w_hh_w, (float*)d_out, out_size);
}